// round 10
// baseline (speedup 1.0000x reference)
#include <cuda_runtime.h>
#include <cuda_fp16.h>

// out[b,o] = min_i max(x[b,i], w[i,o])   (forward of STE expr == hard min-max)
//
// R8 lesson: grid-limited occupancy (24 warps/SM) left L2-latency exposures
// uncovered. This round: warp owns 64 o's (one half2 per lane, LDG.32
// gathers) -> 8192 total warps (~86% occ), same total gather bytes, earlier
// per-warp exit (smaller group), first exit check deferred to k=32.
//
// Fused sort+scan, 4 blocks per row (sort duplicated, smem-only, cheap):
//   1. 256-bin counting sort of x[b,:] by half-rounded value.
//   2. Warp-pruned scan in increasing-x order; warp exits when
//      bin_floor(next x) >= max of its lanes' bests (exact, order-independent).
//   Exit branch warp-uniform -> gather body unpredicated -> LDGs batched.
//
// fp16 RN rounding bounds rel err by ~2^-11 < 1e-3.

#define DB 512
#define DI 512
#define DO 1024
#define NBIN 256

__device__ __half g_wh[DI * DO];   // fp16 w, 1 MB

// ---------- Kernel 1: w fp32 -> fp16, chip-wide MLP ----------
__global__ __launch_bounds__(256) void k_convert(const float* __restrict__ w) {
    int t = blockIdx.x * 256 + threadIdx.x;          // 512 blocks -> 128K threads
    float4 v = reinterpret_cast<const float4*>(w)[t];
    __half2 h0 = __floats2half2_rn(v.x, v.y);
    __half2 h1 = __floats2half2_rn(v.z, v.w);
    reinterpret_cast<uint2*>(g_wh)[t] =
        make_uint2(*reinterpret_cast<unsigned*>(&h0),
                   *reinterpret_cast<unsigned*>(&h1));
}

// ---------- Kernel 2: fused sort + pruned scan (128 thr, 4 warps x 64 o) ----------
__global__ __launch_bounds__(128) void k_fused(const float* __restrict__ x,
                                               float* __restrict__ out) {
    __shared__ uint2 sx[DI];      // bin-ordered {dup-half2(x), idx}, 4 KB
    __shared__ int hist[NBIN];
    __shared__ int offs[NBIN];
    __shared__ int wsum[4];

    const int b = blockIdx.x >> 2;        // 4 blocks per row
    const int quarter = blockIdx.x & 3;   // which 256-o slice
    const int tid = threadIdx.x;
    const int lane = tid & 31, wid = tid >> 5;

    // ---- phase 1: counting sort of x[b,:] (128 threads, 4 elems each) ----
    hist[tid] = 0;
    hist[tid + 128] = 0;
    __syncthreads();

    __half h[4]; int bin[4];
#pragma unroll
    for (int e = 0; e < 4; e++) {
        h[e] = __float2half_rn(x[b * DI + tid + e * 128]);
        bin[e] = min(NBIN - 1, (int)(__half2float(h[e]) * (float)NBIN));
        atomicAdd(&hist[bin[e]], 1);
    }
    __syncthreads();

    // exclusive prefix over 256 bins: thread t owns bin pair (2t, 2t+1)
    const int t2 = tid * 2;
    int h0 = hist[t2], h1 = hist[t2 + 1];
    int pv = h0 + h1;
#pragma unroll
    for (int off = 1; off < 32; off <<= 1) {
        int n = __shfl_up_sync(0xffffffffu, pv, off);
        if (lane >= off) pv += n;
    }
    if (lane == 31) wsum[wid] = pv;
    __syncthreads();
    if (tid < 4) {
        int s = wsum[tid];
#pragma unroll
        for (int off = 1; off < 4; off <<= 1) {
            int n = __shfl_up_sync(0xFu, s, off);
            if (tid >= off) s += n;
        }
        wsum[tid] = s;
    }
    __syncthreads();
    {
        int excl = pv + (wid ? wsum[wid - 1] : 0) - (h0 + h1);
        offs[t2] = excl;
        offs[t2 + 1] = excl + h0;
    }
    __syncthreads();

#pragma unroll
    for (int e = 0; e < 4; e++) {
        unsigned u = (unsigned)__half_as_ushort(h[e]);
        int p = atomicAdd(&offs[bin[e]], 1);
        sx[p] = make_uint2(u | (u << 16), (unsigned)(tid + e * 128));
    }
    __syncthreads();

    // ---- phase 2: pruned scan; this warp owns 64 contiguous o ----
    const unsigned infu = 0x7C007C00u;   // {+inf,+inf} fp16
    __half2 best = *reinterpret_cast<const __half2*>(&infu);

    // o = quarter*256 + wid*64 + lane*2 (+0,1)
    const __half* wb = g_wh + quarter * 256 + wid * 64 + lane * 2;

    for (int k = 0; k < DI; k += 16) {
        if (k >= 32) {   // first check deferred: few warps finish before 32
            // lower bound for all candidates at position >= k
            unsigned nx = sx[k].x & 0xFFFFu;
            float nv = __half2float(__ushort_as_half((unsigned short)nx));
            int nbin = min(NBIN - 1, (int)(nv * (float)NBIN));
            float bound = (float)nbin * (1.0f / (float)NBIN);
            float m = fmaxf(__low2float(best), __high2float(best));
            if (__all_sync(0xffffffffu, bound >= m)) break;   // warp-uniform
        }
        // unpredicated gather body -> 16 LDG.32 front-batched
#pragma unroll
        for (int kk = 0; kk < 16; kk++) {
            uint2 e = sx[k + kk];
            __half2 xv = *reinterpret_cast<__half2*>(&e.x);
            unsigned wv = *reinterpret_cast<const unsigned*>(wb + (e.y << 10));
            best = __hmin2(best, __hmax2(xv, *reinterpret_cast<__half2*>(&wv)));
        }
    }

    float2 r = make_float2(__low2float(best), __high2float(best));
    *reinterpret_cast<float2*>(&out[b * DO + quarter * 256 + wid * 64 + lane * 2]) = r;
}

extern "C" void kernel_launch(void* const* d_in, const int* in_sizes, int n_in,
                              void* d_out, int out_size) {
    const float* x = (const float*)d_in[0];   // [512, 512]
    const float* w = (const float*)d_in[1];   // [512, 1024]
    float* out = (float*)d_out;               // [512, 1024]

    k_convert<<<512, 256>>>(w);               // w -> fp16, ~0.7 us
    k_fused<<<DB * 4, 128>>>(x, out);         // 2048 blocks, 4 per row
}

// round 12
// speedup vs baseline: 1.1097x; 1.1097x over previous
#include <cuda_runtime.h>
#include <cuda_fp16.h>

// out[b,o] = min_i max(x[b,i], w[i,o])   (forward of STE expr == hard min-max)
//
// R10 lesson: 64-o warps raised occupancy (37.8->65.6%) and fixed latency
// coverage, but duplicating the per-row sort 4x ate the gain. This round:
// ONE 512-thread block per row -- sort once (1 elem/thread), then 16 warps
// x 64 o's each for the scan. R8's amortization + R10's parallelism.
// (Resubmit after infra failure; barriers hoisted out of divergent branches.)
//
//   1. 256-bin counting sort of x[b,:] by half-rounded value (smem only).
//   2. Warp-pruned scan in increasing-x order; a warp exits when
//      bin_floor(next x) >= max of its lanes' bests: all remaining i have
//      x_i >= bound >= best, so max(x_i,w) >= best. Exact, order-independent.
//   Exit branch warp-uniform -> gather body unpredicated -> LDGs batched
//   (R4 lesson: per-lane predication collapses MLP).
//
// fp16 RN rounding bounds rel err by ~2^-11 < 1e-3.

#define DB 512
#define DI 512
#define DO 1024
#define NBIN 256

__device__ __half g_wh[DI * DO];   // fp16 w, 1 MB

// ---------- Kernel 1: w fp32 -> fp16, chip-wide MLP ----------
__global__ __launch_bounds__(256) void k_convert(const float* __restrict__ w) {
    int t = blockIdx.x * 256 + threadIdx.x;          // 512 blocks -> 128K threads
    float4 v = reinterpret_cast<const float4*>(w)[t];
    __half2 h0 = __floats2half2_rn(v.x, v.y);
    __half2 h1 = __floats2half2_rn(v.z, v.w);
    reinterpret_cast<uint2*>(g_wh)[t] =
        make_uint2(*reinterpret_cast<unsigned*>(&h0),
                   *reinterpret_cast<unsigned*>(&h1));
}

// ---------- Kernel 2: fused sort + pruned scan (512 thr: sort x1, 16 warps x 64 o) ----------
__global__ __launch_bounds__(512) void k_fused(const float* __restrict__ x,
                                               float* __restrict__ out) {
    __shared__ uint2 sx[DI];      // bin-ordered {dup-half2(x), idx}, 4 KB
    __shared__ int hist[NBIN];
    __shared__ int offs[NBIN];
    __shared__ int wsum[8];

    const int b = blockIdx.x;
    const int tid = threadIdx.x;
    const int lane = tid & 31, wid = tid >> 5;

    // ---- phase 1: counting sort of x[b,:], one element per thread ----
    if (tid < NBIN) hist[tid] = 0;
    __syncthreads();

    __half h = __float2half_rn(x[b * DI + tid]);
    int bin = min(NBIN - 1, (int)(__half2float(h) * (float)NBIN));
    atomicAdd(&hist[bin], 1);
    __syncthreads();

    // exclusive prefix over 256 bins; ALL barriers executed uniformly.
    int pv = 0;
    if (tid < NBIN) {
        pv = hist[tid];
#pragma unroll
        for (int off = 1; off < 32; off <<= 1) {
            int n = __shfl_up_sync(0xffffffffu, pv, off);
            if (lane >= off) pv += n;
        }
        if (lane == 31) wsum[wid] = pv;
    }
    __syncthreads();
    if (tid < 8) {
        int s = wsum[tid];
#pragma unroll
        for (int off = 1; off < 8; off <<= 1) {
            int n = __shfl_up_sync(0xffu, s, off);
            if (tid >= off) s += n;
        }
        wsum[tid] = s;
    }
    __syncthreads();
    if (tid < NBIN)
        offs[tid] = pv + (wid ? wsum[wid - 1] : 0) - hist[tid];
    __syncthreads();

    {
        unsigned u = (unsigned)__half_as_ushort(h);
        int p = atomicAdd(&offs[bin], 1);
        sx[p] = make_uint2(u | (u << 16), (unsigned)tid);
    }
    __syncthreads();

    // ---- phase 2: pruned scan; warp wid owns o = wid*64 .. wid*64+63 ----
    const unsigned infu = 0x7C007C00u;   // {+inf,+inf} fp16
    __half2 best = *reinterpret_cast<const __half2*>(&infu);

    const __half* wb = g_wh + wid * 64 + lane * 2;

    for (int k = 0; k < DI; k += 16) {
        if (k) {
            // lower bound for all candidates at position >= k: same-or-later
            // bin, so value >= bin_floor(value at position k).
            unsigned nx = sx[k].x & 0xFFFFu;
            float nv = __half2float(__ushort_as_half((unsigned short)nx));
            int nbin = min(NBIN - 1, (int)(nv * (float)NBIN));
            float bound = (float)nbin * (1.0f / (float)NBIN);
            float m = fmaxf(__low2float(best), __high2float(best));
            if (__all_sync(0xffffffffu, bound >= m)) break;   // warp-uniform
        }
        // unpredicated gather body -> 16 LDG.32 front-batched
#pragma unroll
        for (int kk = 0; kk < 16; kk++) {
            uint2 e = sx[k + kk];
            __half2 xv = *reinterpret_cast<__half2*>(&e.x);
            unsigned wv = *reinterpret_cast<const unsigned*>(wb + (e.y << 10));
            best = __hmin2(best, __hmax2(xv, *reinterpret_cast<__half2*>(&wv)));
        }
    }

    float2 r = make_float2(__low2float(best), __high2float(best));
    *reinterpret_cast<float2*>(&out[b * DO + wid * 64 + lane * 2]) = r;
}

extern "C" void kernel_launch(void* const* d_in, const int* in_sizes, int n_in,
                              void* d_out, int out_size) {
    const float* x = (const float*)d_in[0];   // [512, 512]
    const float* w = (const float*)d_in[1];   // [512, 1024]
    float* out = (float*)d_out;               // [512, 1024]

    k_convert<<<512, 256>>>(w);               // w -> fp16, ~0.7 us
    k_fused<<<DB, 512>>>(x, out);             // one block per row, 16 warps
}

// round 13
// speedup vs baseline: 1.1341x; 1.0220x over previous
#include <cuda_runtime.h>
#include <cuda_fp16.h>

// out[b,o] = min_i max(x[b,i], w[i,o])   (forward of STE expr == hard min-max)
//
// R12 falsified the occupancy theory (occ 37.8->67% made k_fused slower).
// Best measured geometry is R8: 8 warps x 128 o, LDG.64 fp16 gathers.
// This round keeps that scan and removes the two measured overheads:
//   (1) convert-kernel launch gap (~1.7us): ONE kernel; each block converts
//       its 2KB slice of w->fp16, then an epoch-based grid barrier (atomic
//       counter, target=(my/512+1)*512 so graph replays self-reset). The
//       per-row sort runs between arrive and spin, hiding the wait.
//       Deadlock-safe: 512 blocks fit in wave 1 (>=4 blocks/SM at 256thr).
//   (2) exit overshoot: first batch 16 candidates, then check every 8
//       (checks every 16 wasted ~8 candidates past the true exit ~22).
//
// Scan: candidates in increasing-x (256-bin bucket) order; a warp exits when
// bin_floor(next x) >= max of its lanes' bests: all remaining i have
// x_i >= bound >= best so max(x_i,w) >= best. Exact, order-independent.
// Exit branch warp-uniform -> gather body unpredicated -> LDGs batched.
//
// fp16 RN rounding bounds rel err by ~2^-11 < 1e-3.

#define DB 512
#define DI 512
#define DO 1024
#define NBIN 256
#define NBLK 512ULL

__device__ __half g_wh[DI * DO];                 // fp16 w, 1 MB
__device__ unsigned long long g_arrive = 0ULL;   // grid-barrier epoch counter

__global__ __launch_bounds__(256) void k_fused(const float* __restrict__ x,
                                               const float* __restrict__ w,
                                               float* __restrict__ out) {
    __shared__ uint2 sx[DI];      // bin-ordered {dup-half2(x), idx}, 4 KB
    __shared__ int hist[NBIN];
    __shared__ int offs[NBIN];
    __shared__ int wsum[8];
    __shared__ unsigned long long s_target;

    const int b = blockIdx.x;
    const int tid = threadIdx.x;
    const int lane = tid & 31, wid = tid >> 5;

    // ---- phase 0: convert this block's 1/512 slice of w to fp16 ----
    {
        int t = b * 256 + tid;                       // float4 index, 131072 total
        float4 v = reinterpret_cast<const float4*>(w)[t];
        __half2 h0 = __floats2half2_rn(v.x, v.y);
        __half2 h1 = __floats2half2_rn(v.z, v.w);
        reinterpret_cast<uint2*>(g_wh)[t] =
            make_uint2(*reinterpret_cast<unsigned*>(&h0),
                       *reinterpret_cast<unsigned*>(&h1));
        __threadfence();                             // make slice GPU-visible
    }
    __syncthreads();
    if (tid == 0) {
        unsigned long long my = atomicAdd(&g_arrive, 1ULL);
        s_target = (my / NBLK + 1ULL) * NBLK;        // epoch end for this launch
    }

    // ---- phase 1: counting sort of x[b,:] (overlaps other blocks' converts) ----
    hist[tid] = 0;
    __syncthreads();

    __half h0s = __float2half_rn(x[b * DI + tid]);
    __half h1s = __float2half_rn(x[b * DI + tid + 256]);
    int bin0 = min(NBIN - 1, (int)(__half2float(h0s) * (float)NBIN));
    int bin1 = min(NBIN - 1, (int)(__half2float(h1s) * (float)NBIN));
    atomicAdd(&hist[bin0], 1);
    atomicAdd(&hist[bin1], 1);
    __syncthreads();

    // exclusive prefix over 256 bins (thread t owns bin t)
    int pv = hist[tid];
#pragma unroll
    for (int off = 1; off < 32; off <<= 1) {
        int n = __shfl_up_sync(0xffffffffu, pv, off);
        if (lane >= off) pv += n;
    }
    if (lane == 31) wsum[wid] = pv;
    __syncthreads();
    if (tid < 8) {
        int s = wsum[tid];
#pragma unroll
        for (int off = 1; off < 8; off <<= 1) {
            int n = __shfl_up_sync(0xffu, s, off);
            if (tid >= off) s += n;
        }
        wsum[tid] = s;
    }
    __syncthreads();
    offs[tid] = pv + (wid ? wsum[wid - 1] : 0) - hist[tid];
    __syncthreads();

    {
        unsigned u0 = (unsigned)__half_as_ushort(h0s);
        unsigned u1 = (unsigned)__half_as_ushort(h1s);
        int p0 = atomicAdd(&offs[bin0], 1);
        sx[p0] = make_uint2(u0 | (u0 << 16), (unsigned)tid);
        int p1 = atomicAdd(&offs[bin1], 1);
        sx[p1] = make_uint2(u1 | (u1 << 16), (unsigned)(tid + 256));
    }

    // ---- grid barrier: wait for all 512 conversion slices ----
    if (tid == 0) {
        unsigned long long tgt = s_target;
        while (atomicAdd(&g_arrive, 0ULL) < tgt) { }
    }
    __syncthreads();
    __threadfence();   // order: counter observation before g_wh reads

    // ---- phase 2: pruned scan; warp wid owns o = wid*128 .. +127 ----
    const unsigned infu = 0x7C007C00u;   // {+inf,+inf} fp16
    __half2 best0 = *reinterpret_cast<const __half2*>(&infu);
    __half2 best1 = best0;

    const __half* wb = g_wh + wid * 128 + lane * 4;

    // first 16 candidates unchecked (warps essentially never exit earlier)
#pragma unroll
    for (int kk = 0; kk < 16; kk++) {
        uint2 e = sx[kk];
        __half2 xv = *reinterpret_cast<__half2*>(&e.x);
        uint2 wv = *reinterpret_cast<const uint2*>(wb + (e.y << 10));
        best0 = __hmin2(best0, __hmax2(xv, *reinterpret_cast<__half2*>(&wv.x)));
        best1 = __hmin2(best1, __hmax2(xv, *reinterpret_cast<__half2*>(&wv.y)));
    }

#pragma unroll 1
    for (int k = 16; k < DI; k += 8) {
        // lower bound for all candidates at position >= k: same-or-later bin,
        // so value >= bin_floor(value at position k).
        unsigned nx = sx[k].x & 0xFFFFu;
        float nv = __half2float(__ushort_as_half((unsigned short)nx));
        int nbin = min(NBIN - 1, (int)(nv * (float)NBIN));
        float bound = (float)nbin * (1.0f / (float)NBIN);
        __half2 m2 = __hmax2(best0, best1);
        float m = fmaxf(__low2float(m2), __high2float(m2));
        if (__all_sync(0xffffffffu, bound >= m)) break;   // warp-uniform exit

        // unpredicated gather body -> 8 LDG.64 front-batched
#pragma unroll
        for (int kk = 0; kk < 8; kk++) {
            uint2 e = sx[k + kk];
            __half2 xv = *reinterpret_cast<__half2*>(&e.x);
            uint2 wv = *reinterpret_cast<const uint2*>(wb + (e.y << 10));
            best0 = __hmin2(best0, __hmax2(xv, *reinterpret_cast<__half2*>(&wv.x)));
            best1 = __hmin2(best1, __hmax2(xv, *reinterpret_cast<__half2*>(&wv.y)));
        }
    }

    float4 r;
    r.x = __low2float(best0);  r.y = __high2float(best0);
    r.z = __low2float(best1);  r.w = __high2float(best1);
    *reinterpret_cast<float4*>(&out[b * DO + wid * 128 + lane * 4]) = r;
}

extern "C" void kernel_launch(void* const* d_in, const int* in_sizes, int n_in,
                              void* d_out, int out_size) {
    const float* x = (const float*)d_in[0];   // [512, 512]
    const float* w = (const float*)d_in[1];   // [512, 1024]
    float* out = (float*)d_out;               // [512, 1024]

    k_fused<<<DB, 256>>>(x, w, out);          // single launch, grid barrier inside
}

// round 14
// speedup vs baseline: 1.2932x; 1.1404x over previous
#include <cuda_runtime.h>
#include <cuda_fp16.h>

// out[b,o] = min_i max(x[b,i], w[i,o])   (forward of STE expr == hard min-max)
//
// R13 lesson: in-kernel grid barrier serialized the grid (issue 29%) -- the
// two-launch shape is cheaper. R8 geometry (8 warps x 128 o, LDG.64 fp16
// gathers) remains best; its residual cost is that each gather round was
// SERIALIZED on the exit branch (accumulators -> ballot -> next round's LDGs).
//
// This round: SOFTWARE-PIPELINED scan. Each iteration issues batch k+1's
// gathers (depend only on smem) BEFORE the exit check for batch k resolves,
// overlapping the L2 round-trip with the next batch's memory time. Batch=8
// halves exit overshoot; an exit wastes only already-in-flight loads.
//
// Scan order: increasing x (256-bin bucket sort). Warp exits when
// bin_floor(next x) >= max of its lanes' bests: all remaining i have
// x_i >= bound >= best, so max(x_i,w) >= best. Exact, order-independent.
// fp16 RN rounding bounds rel err by ~2^-11 < 1e-3.

#define DB 512
#define DI 512
#define DO 1024
#define NBIN 256

__device__ __half g_wh[DI * DO];   // fp16 w, 1 MB

// ---------- Kernel 1: w fp32 -> fp16, chip-wide MLP, ~0.5us ----------
__global__ __launch_bounds__(256) void k_convert(const float* __restrict__ w) {
    int t = blockIdx.x * 256 + threadIdx.x;          // 512 blocks, 1 float4 each
    float4 v = reinterpret_cast<const float4*>(w)[t];
    __half2 h0 = __floats2half2_rn(v.x, v.y);
    __half2 h1 = __floats2half2_rn(v.z, v.w);
    reinterpret_cast<uint2*>(g_wh)[t] =
        make_uint2(*reinterpret_cast<unsigned*>(&h0),
                   *reinterpret_cast<unsigned*>(&h1));
}

// ---------- Kernel 2: fused sort + pipelined pruned scan ----------
__global__ __launch_bounds__(256) void k_fused(const float* __restrict__ x,
                                               float* __restrict__ out) {
    __shared__ uint2 sx[DI];      // bin-ordered {dup-half2(x), idx}, 4 KB
    __shared__ int hist[NBIN];
    __shared__ int offs[NBIN];
    __shared__ int wsum[8];

    const int b = blockIdx.x;
    const int tid = threadIdx.x;
    const int lane = tid & 31, wid = tid >> 5;

    // ---- phase 1: counting sort of x[b,:] by half-rounded value ----
    hist[tid] = 0;
    __syncthreads();

    __half h0s = __float2half_rn(x[b * DI + tid]);
    __half h1s = __float2half_rn(x[b * DI + tid + 256]);
    int bin0 = min(NBIN - 1, (int)(__half2float(h0s) * (float)NBIN));
    int bin1 = min(NBIN - 1, (int)(__half2float(h1s) * (float)NBIN));
    atomicAdd(&hist[bin0], 1);
    atomicAdd(&hist[bin1], 1);
    __syncthreads();

    // exclusive prefix over 256 bins (thread t owns bin t)
    int pv = hist[tid];
#pragma unroll
    for (int off = 1; off < 32; off <<= 1) {
        int n = __shfl_up_sync(0xffffffffu, pv, off);
        if (lane >= off) pv += n;
    }
    if (lane == 31) wsum[wid] = pv;
    __syncthreads();
    if (tid < 8) {
        int s = wsum[tid];
#pragma unroll
        for (int off = 1; off < 8; off <<= 1) {
            int n = __shfl_up_sync(0xffu, s, off);
            if (tid >= off) s += n;
        }
        wsum[tid] = s;
    }
    __syncthreads();
    offs[tid] = pv + (wid ? wsum[wid - 1] : 0) - hist[tid];
    __syncthreads();

    {
        unsigned u0 = (unsigned)__half_as_ushort(h0s);
        unsigned u1 = (unsigned)__half_as_ushort(h1s);
        int p0 = atomicAdd(&offs[bin0], 1);
        sx[p0] = make_uint2(u0 | (u0 << 16), (unsigned)tid);
        int p1 = atomicAdd(&offs[bin1], 1);
        sx[p1] = make_uint2(u1 | (u1 << 16), (unsigned)(tid + 256));
    }
    __syncthreads();

    // ---- phase 2: software-pipelined pruned scan; warp owns 128 o ----
    const unsigned infu = 0x7C007C00u;   // {+inf,+inf} fp16
    __half2 best0 = *reinterpret_cast<const __half2*>(&infu);
    __half2 best1 = best0;

    const __half* wb = g_wh + wid * 128 + lane * 4;

    __half2 cx[8]; uint2 cw[8];          // current batch (in registers)

    // prologue: load batch 0
#pragma unroll
    for (int kk = 0; kk < 8; kk++) {
        uint2 e = sx[kk];
        cx[kk] = *reinterpret_cast<__half2*>(&e.x);
        cw[kk] = *reinterpret_cast<const uint2*>(wb + (e.y << 10));
    }

#pragma unroll 1
    for (int k = 0;;) {
        const int kn = k + 8;

        // (1) issue NEXT batch's gathers first -- they depend only on smem,
        //     so they fly while the accumulate+check below resolves.
        __half2 nx2[8]; uint2 nw[8];
        if (kn < DI) {                           // warp-uniform guard
#pragma unroll
            for (int kk = 0; kk < 8; kk++) {
                uint2 e = sx[kn + kk];
                nx2[kk] = *reinterpret_cast<__half2*>(&e.x);
                nw[kk]  = *reinterpret_cast<const uint2*>(wb + (e.y << 10));
            }
        }

        // (2) accumulate current batch
#pragma unroll
        for (int kk = 0; kk < 8; kk++) {
            best0 = __hmin2(best0, __hmax2(cx[kk], *reinterpret_cast<__half2*>(&cw[kk].x)));
            best1 = __hmin2(best1, __hmax2(cx[kk], *reinterpret_cast<__half2*>(&cw[kk].y)));
        }

        if (kn >= DI) break;

        // (3) exit check for remaining candidates (positions >= kn):
        //     same-or-later bin, so value >= bin_floor(value at kn).
        unsigned nxv = sx[kn].x & 0xFFFFu;
        float nv = __half2float(__ushort_as_half((unsigned short)nxv));
        int nbin = min(NBIN - 1, (int)(nv * (float)NBIN));
        float bound = (float)nbin * (1.0f / (float)NBIN);
        __half2 m2 = __hmax2(best0, best1);
        float m = fmaxf(__low2float(m2), __high2float(m2));
        if (__all_sync(0xffffffffu, bound >= m)) break;   // warp-uniform

        // (4) rotate buffers
#pragma unroll
        for (int kk = 0; kk < 8; kk++) { cx[kk] = nx2[kk]; cw[kk] = nw[kk]; }
        k = kn;
    }

    float4 r;
    r.x = __low2float(best0);  r.y = __high2float(best0);
    r.z = __low2float(best1);  r.w = __high2float(best1);
    *reinterpret_cast<float4*>(&out[b * DO + wid * 128 + lane * 4]) = r;
}

extern "C" void kernel_launch(void* const* d_in, const int* in_sizes, int n_in,
                              void* d_out, int out_size) {
    const float* x = (const float*)d_in[0];   // [512, 512]
    const float* w = (const float*)d_in[1];   // [512, 1024]
    float* out = (float*)d_out;               // [512, 1024]

    k_convert<<<512, 256>>>(w);               // w -> fp16, ~0.5 us
    k_fused<<<DB, 256>>>(x, out);             // one block per row
}